// round 17
// baseline (speedup 1.0000x reference)
#include <cuda_runtime.h>
#include <math.h>

#define L    128
#define NB   64
#define DD   768
#define IN   64
#define OUTD 64
#define NO   32
#define EPSV 1e-8f
#define NCH  16         // l-chunks
#define LCH  8          // l per chunk

// votetr shared-memory layout (floats)
#define VSM_BS   (64 * 66)                  // As size: 4224
#define VSM_STG  (VSM_BS + 2 * 4096)        // after As + double-buffered Bs: 12416
#define VSM_TOT  (VSM_STG + 8 * 4096)       // + 8 staged o-tiles: 45184 floats (180736 B)

// ---------------- scratch (device globals) -----------------------------------
__device__ float g_mu_in[L * NB * IN];                 // (l, n, i)
__device__ float g_fa[L * NB];                         // (l, n)
__device__ float g_Vt[(size_t)NB * L * OUTD * NO];     // (n, l, j, o)  64 MB
__device__ float g_mut[NB * OUTD * NO];                // (n, j, o)
__device__ float g_ivt[NB * OUTD * NO];                // (n, j, o) : 1/(2var+eps)
__device__ float g_a[NB * NO];                         // (n, o) activation logit
__device__ float g_lvp[NB * 4 * NO];                   // (n, jg, o) partial sum log var
__device__ float g_q1[NB * NCH * OUTD * NO];           // chunk partials 8 MB
__device__ float g_q2[NB * NCH * OUTD * NO];           // 8 MB
__device__ float g_q0[NB * NCH * NO];
__device__ float g_qbu[NB * NCH * NO];
__device__ float g_qfa[NB * NCH];

// ---------------- packed f32x2 helpers ---------------------------------------
__device__ __forceinline__ unsigned long long pk(float x, float y) {
    unsigned long long r; asm("mov.b64 %0, {%1, %2};" : "=l"(r) : "f"(x), "f"(y)); return r;
}
__device__ __forceinline__ void fma2(unsigned long long& d, unsigned long long a, unsigned long long b) {
    asm("fma.rn.f32x2 %0, %1, %2, %0;" : "+l"(d) : "l"(a), "l"(b));
}
__device__ __forceinline__ float2 upk(unsigned long long v) {
    float2 r; asm("mov.b64 {%0, %1}, %2;" : "=f"(r.x), "=f"(r.y) : "l"(v)); return r;
}

// ---------------- kernel 1: a_in + mu_in (n-split 2, fused score) -------------
__global__ __launch_bounds__(256) void front_kernel(
    const float* __restrict__ x,      // (N, L, D)
    const float* __restrict__ Wsc,    // (L, D)
    const float* __restrict__ Bsc,    // (L)
    const float* __restrict__ Wc,     // (L, D, IN)
    const float* __restrict__ Bc)     // (L, IN)
{
    __shared__ __align__(8) float As[32][34];      // [k][n-half]
    __shared__ __align__(16) float Bs[32][64];     // [k][i]
    __shared__ float s_ws[32];
    __shared__ float s_sc[8][32];

    const int bid = blockIdx.x;
    const int l   = bid >> 1;
    const int n0  = (bid & 1) * 32;
    const int tid = threadIdx.x;
    const int tn  = tid >> 4;
    const int tj  = tid & 15;

    const int sq = tid >> 5, sn = tid & 31;
    float sc = 0.f;

    unsigned long long acc[4] = {};

    for (int kk = 0; kk < DD; kk += 32) {
        #pragma unroll
        for (int p = 0; p < 4; p++) {
            int e = tid + p * 256;
            int n = e >> 5, k = e & 31;
            As[k][n] = __ldcs(&x[((size_t)(n0 + n) * L + l) * DD + kk + k]);
        }
        #pragma unroll
        for (int p = 0; p < 8; p++) {
            int e = tid + p * 256;
            int k = e >> 6, i = e & 63;
            Bs[k][i] = __ldcs(&Wc[(size_t)l * DD * IN + (size_t)(kk + k) * IN + i]);
        }
        if (tid < 32) s_ws[tid] = Wsc[(size_t)l * DD + kk + tid];
        __syncthreads();

        #pragma unroll
        for (int k = 0; k < 32; k++) {
            float2 a0 = reinterpret_cast<const float2*>(&As[k][0])[tn];
            unsigned long long A0;
            asm("mov.b64 %0, {%1, %2};" : "=l"(A0) : "f"(a0.x), "f"(a0.y));
            float4 b = reinterpret_cast<const float4*>(&Bs[k][0])[tj];
            unsigned long long B0 = pk(b.x, b.x), B1 = pk(b.y, b.y),
                               B2 = pk(b.z, b.z), B3 = pk(b.w, b.w);
            fma2(acc[0], A0, B0); fma2(acc[1], A0, B1);
            fma2(acc[2], A0, B2); fma2(acc[3], A0, B3);
        }

        #pragma unroll
        for (int k4 = 0; k4 < 4; k4++)
            sc = fmaf(As[sq * 4 + k4][sn], s_ws[sq * 4 + k4], sc);
        __syncthreads();
    }

    #pragma unroll
    for (int c = 0; c < 4; c++) {
        int i = tj * 4 + c;
        float2 v2 = upk(acc[c]);
        float bb = Bc[l * IN + i];
        int n = n0 + tn * 2;
        float v0 = v2.x + bb, v1 = v2.y + bb;
        g_mu_in[(size_t)l * NB * IN + (size_t)n * IN + i]       = v0 * normcdff(v0);
        g_mu_in[(size_t)l * NB * IN + (size_t)(n + 1) * IN + i] = v1 * normcdff(v1);
    }

    s_sc[sq][sn] = sc;
    __syncthreads();
    if (tid < 32) {
        float s = Bsc[l];
        #pragma unroll
        for (int q = 0; q < 8; q++) s += s_sc[q][tid];
        g_fa[l * NB + n0 + tid] = 1.f / (1.f + expf(-s));
    }
}

// ---------------- kernel 2: fused votes + transpose ---------------------------
// grid = L (block per l), block = 512, dyn smem = VSM_TOT floats.
// Loops o with double-buffered Wvote tile; stages 8 o-tiles in smem; flushes
// Vt(n,l,j,o) with full-sector 32B writes per (n,j). V never hits DRAM.
__global__ __launch_bounds__(512) void votetr_kernel(
    const float* __restrict__ Wv,    // (L, NO, IN, OUT)
    const float* __restrict__ Bv)    // (L, NO, OUT)
{
    extern __shared__ float sm[];
    float* As  = sm;                   // [i][n] 64 x 66
    float* Bs  = sm + VSM_BS;          // 2 x 4096 double buffer
    float* stg = sm + VSM_STG;         // [oo][n*64+j] 8 x 4096

    const int l   = blockIdx.x;
    const int tid = threadIdx.x;
    const int tn  = tid >> 4;          // 0..31 -> n-pair base 2*tn
    const int tj  = tid & 15;          // j quad

    // load As = mu_in[l] transposed to [i][n]
    {
        const float* A = g_mu_in + (size_t)l * NB * IN;
        #pragma unroll
        for (int p = 0; p < 8; p++) {
            int e = tid + p * 512;                 // e = n*64 + i
            As[(e & 63) * 66 + (e >> 6)] = A[e];
        }
    }

    const float4* Wv4 = reinterpret_cast<const float4*>(Wv + (size_t)l * NO * IN * OUTD);

    // prologue: o=0 tile -> regs -> Bs[0]
    float4 r0 = __ldcs(&Wv4[tid]);
    float4 r1 = __ldcs(&Wv4[tid + 512]);
    {
        float4* B0 = reinterpret_cast<float4*>(Bs);
        B0[tid] = r0; B0[tid + 512] = r1;
    }
    __syncthreads();

    int buf = 0;
    for (int o = 0; o < NO; o++) {
        // prefetch next o tile while computing
        if (o + 1 < NO) {
            const float4* Wn = Wv4 + (size_t)(o + 1) * 1024;
            r0 = __ldcs(&Wn[tid]);
            r1 = __ldcs(&Wn[tid + 512]);
        }

        const float* Bc = Bs + buf * 4096;
        unsigned long long acc[4] = {};
        #pragma unroll
        for (int i = 0; i < 64; i++) {
            float2 a = *reinterpret_cast<const float2*>(As + i * 66 + tn * 2);
            unsigned long long A0;
            asm("mov.b64 %0, {%1, %2};" : "=l"(A0) : "f"(a.x), "f"(a.y));
            float4 b = reinterpret_cast<const float4*>(Bc + i * 64)[tj];
            fma2(acc[0], A0, pk(b.x, b.x));
            fma2(acc[1], A0, pk(b.y, b.y));
            fma2(acc[2], A0, pk(b.z, b.z));
            fma2(acc[3], A0, pk(b.w, b.w));
        }

        float4 bias = __ldcs(reinterpret_cast<const float4*>(
            Bv + ((size_t)l * NO + o) * OUTD) + tj);
        float2 c0 = upk(acc[0]), c1 = upk(acc[1]), c2 = upk(acc[2]), c3 = upk(acc[3]);
        const int oo = o & 7;
        float* sp = stg + oo * 4096 + (tn * 2) * 64 + tj * 4;
        *reinterpret_cast<float4*>(sp) =
            make_float4(c0.x + bias.x, c1.x + bias.y, c2.x + bias.z, c3.x + bias.w);
        *reinterpret_cast<float4*>(sp + 64) =
            make_float4(c0.y + bias.x, c1.y + bias.y, c2.y + bias.z, c3.y + bias.w);

        // store prefetched tile into the other buffer
        if (o + 1 < NO) {
            float4* Bn = reinterpret_cast<float4*>(Bs + (buf ^ 1) * 4096);
            Bn[tid] = r0; Bn[tid + 512] = r1;
        }
        __syncthreads();
        buf ^= 1;

        if (oo == 7) {
            const int og = o >> 3;
            #pragma unroll
            for (int p = 0; p < 8; p++) {
                int cell = tid + p * 512;          // n = cell>>6, j = cell&63
                float4 w0, w1;
                w0.x = stg[0 * 4096 + cell]; w0.y = stg[1 * 4096 + cell];
                w0.z = stg[2 * 4096 + cell]; w0.w = stg[3 * 4096 + cell];
                w1.x = stg[4 * 4096 + cell]; w1.y = stg[5 * 4096 + cell];
                w1.z = stg[6 * 4096 + cell]; w1.w = stg[7 * 4096 + cell];
                float* dst = g_Vt +
                    (((size_t)(cell >> 6) * L + l) * OUTD + (cell & 63)) * NO + og * 8;
                *reinterpret_cast<float4*>(dst)     = w0;
                *reinterpret_cast<float4*>(dst + 4) = w1;
            }
            __syncthreads();   // flush reads done before next group's stage writes
        }
    }
}

// ---------------- kernel 2b: E-step 0 (uniform R, streaming over Vt) ----------
// grid = NB*NCH (bid: n = bid>>4, c = bid&15), block = 256.
// Warp w owns j-slice [w*8, w*8+8); lane = o. Same access pattern as re phase 2.
__global__ __launch_bounds__(256) void em0_kernel(const float* __restrict__ bu)
{
    const int bid = blockIdx.x;
    const int n = bid >> 4, c = bid & (NCH - 1);
    const int tid = threadIdx.x;
    const int w = tid >> 5, lane = tid & 31;
    const int j0 = w * 8;

    float s1[8] = {}, s2[8] = {};
    #pragma unroll
    for (int li = 0; li < LCH; li++) {
        int l = c * LCH + li;
        float D = g_fa[l * NB + n] * (1.f / 32.f);
        const float* vb = g_Vt + (((size_t)n * L + l) * OUTD + j0) * NO + lane;
        #pragma unroll
        for (int jj = 0; jj < 8; jj++) {
            float v = vb[jj * NO];
            float dv = D * v;
            s1[jj] += dv;
            s2[jj] = fmaf(dv, v, s2[jj]);
        }
    }
    float* q1 = g_q1 + ((size_t)bid * OUTD + j0) * NO + lane;
    float* q2 = g_q2 + ((size_t)bid * OUTD + j0) * NO + lane;
    #pragma unroll
    for (int jj = 0; jj < 8; jj++) { q1[jj * NO] = s1[jj]; q2[jj * NO] = s2[jj]; }

    if (w == 0) {
        float s0 = 0.f, sbu = 0.f, sfa = 0.f;
        #pragma unroll
        for (int li = 0; li < LCH; li++) {
            int ll = c * LCH + li;
            float fa = g_fa[ll * NB + n];
            s0 += fa * (1.f / 32.f);
            sbu = fmaf(bu[ll], fa * (1.f / 32.f), sbu);
            sfa += fa;
        }
        g_q0[bid * NO + lane]  = s0;
        g_qbu[bid * NO + lane] = sbu;
        if (lane == 0) g_qfa[bid] = sfa;
    }
}

// ---------------- kernel 3: fused route + EM partials (lane = o) --------------
// grid = NB*NCH (bid: n = bid>>4, c = bid&15), block = 256 (8 warps, 1 l each).
__global__ __launch_bounds__(256) void re_kernel(const float* __restrict__ bu)
{
    __shared__ float s_mu[OUTD * NO];   // (j, o)
    __shared__ float s_iv[OUTD * NO];
    __shared__ float s_C[NO];
    __shared__ float s_D[LCH][NO];

    const int bid = blockIdx.x;
    const int n = bid >> 4, c = bid & (NCH - 1);
    const int tid = threadIdx.x;
    const int w = tid >> 5, lane = tid & 31;

    {
        const float4* ms = reinterpret_cast<const float4*>(g_mut + (size_t)n * OUTD * NO);
        const float4* is = reinterpret_cast<const float4*>(g_ivt + (size_t)n * OUTD * NO);
        float4* md = reinterpret_cast<float4*>(s_mu);
        float4* id = reinterpret_cast<float4*>(s_iv);
        md[tid] = ms[tid]; md[tid + 256] = ms[tid + 256];
        id[tid] = is[tid]; id[tid + 256] = is[tid + 256];
        if (tid < NO) {
            float a = g_a[n * NO + tid];
            float slv = g_lvp[(n * 4 + 0) * NO + tid] + g_lvp[(n * 4 + 1) * NO + tid]
                      + g_lvp[(n * 4 + 2) * NO + tid] + g_lvp[(n * 4 + 3) * NO + tid];
            float lsig = (a > 0.f) ? -log1pf(expf(-a)) : a - log1pf(expf(a));
            s_C[tid] = lsig - 1.f - 0.5f * 3.14159265358979323846f - 0.5f * slv;
        }
        __syncthreads();
    }

    // phase 1: warp w -> l = c*8 + w; lane = o; zero barriers
    const int l = c * LCH + w;
    const float fa = g_fa[l * NB + n];
    float D;
    {
        const float* vb = g_Vt + ((size_t)n * L + l) * OUTD * NO + lane;
        float t = 0.f;
        #pragma unroll
        for (int j = 0; j < OUTD; j++) {
            float v = vb[j * NO];
            float d = v - s_mu[j * NO + lane];
            t = fmaf(d * d, s_iv[j * NO + lane], t);
        }
        float lg = s_C[lane] - t;
        float mx = lg;
        #pragma unroll
        for (int off = 16; off; off >>= 1) mx = fmaxf(mx, __shfl_xor_sync(0xffffffffu, mx, off));
        float e = expf(lg - mx);
        float ss = e;
        #pragma unroll
        for (int off = 16; off; off >>= 1) ss += __shfl_xor_sync(0xffffffffu, ss, off);
        D = fa * (e / ss);
    }
    s_D[w][lane] = D;
    __syncthreads();

    // phase 2: warp w owns j-slice [w*8, w*8+8); lane = o; accumulate over 8 l
    float s1[8] = {}, s2[8] = {};
    const int j0 = w * 8;
    #pragma unroll
    for (int li = 0; li < LCH; li++) {
        float Dl = s_D[li][lane];
        const float* vb = g_Vt + (((size_t)n * L + c * LCH + li) * OUTD + j0) * NO + lane;
        #pragma unroll
        for (int jj = 0; jj < 8; jj++) {
            float v = vb[jj * NO];
            float dv = Dl * v;
            s1[jj] += dv;
            s2[jj] = fmaf(dv, v, s2[jj]);
        }
    }
    float* q1 = g_q1 + ((size_t)bid * OUTD + j0) * NO + lane;
    float* q2 = g_q2 + ((size_t)bid * OUTD + j0) * NO + lane;
    #pragma unroll
    for (int jj = 0; jj < 8; jj++) { q1[jj * NO] = s1[jj]; q2[jj * NO] = s2[jj]; }

    if (w == 0) {
        float s0 = 0.f, sbu = 0.f, sfa = 0.f;
        #pragma unroll
        for (int li = 0; li < LCH; li++) {
            int ll = c * LCH + li;
            float Dl = s_D[li][lane];
            s0 += Dl;
            sbu = fmaf(bu[ll], Dl, sbu);
            sfa += g_fa[ll * NB + n];
        }
        g_q0[bid * NO + lane]  = s0;
        g_qbu[bid * NO + lane] = sbu;
        if (lane == 0) g_qfa[bid] = sfa;
    }
}

// ---------------- kernel 4: finalize EM (parallel, one (j,o) per thread) ------
// grid = NB*4 (bid: n = bid>>2, jg = bid&3), block = 512.
__global__ __launch_bounds__(512) void fin_kernel(
    const float* __restrict__ bi, int write_out, float* __restrict__ out)
{
    const int bid = blockIdx.x;
    const int n = bid >> 2, jg = bid & 3;
    const int tid = threadIdx.x;
    const int jj = tid >> 5, o = tid & 31;
    const int j = jg * 16 + jj;

    float s0 = 0.f, sbu = 0.f, sfa = 0.f;
    #pragma unroll
    for (int c = 0; c < NCH; c++) {
        s0  += g_q0[(n * NCH + c) * NO + o];
        sbu += g_qbu[(n * NCH + c) * NO + o];
        sfa += g_qfa[n * NCH + c];
    }
    float denom = s0 + EPSV;
    float a = sbu - bi[o] * (sfa - s0);

    float s1 = 0.f, s2 = 0.f;
    #pragma unroll
    for (int c = 0; c < NCH; c++) {
        size_t p = (((size_t)(n * NCH + c)) * OUTD + j) * NO + o;
        s1 += g_q1[p];
        s2 += g_q2[p];
    }
    float m   = s1 / denom;
    float var = fmaxf((s2 - 2.f * m * s1 + m * m * s0) / denom, 0.f);

    if (write_out) {
        out[NB * NO + ((size_t)n * NO + o) * OUTD + j] = m;    // mu_out (N, NO, OUT)
        if (jj == 0 && jg == 0) out[n * NO + o] = a;           // a_out (N, NO)
    } else {
        g_mut[((size_t)n * OUTD + j) * NO + o] = m;
        g_ivt[((size_t)n * OUTD + j) * NO + o] = 1.f / (2.f * var + EPSV);

        float lv = logf(var + EPSV);
        __shared__ float s_lv[16][NO];
        s_lv[jj][o] = lv;
        __syncthreads();
        if (jj == 0) {
            float slv = 0.f;
            #pragma unroll
            for (int k = 0; k < 16; k++) slv += s_lv[k][o];
            g_lvp[(n * 4 + jg) * NO + o] = slv;
            if (jg == 0) g_a[n * NO + o] = a;
        }
    }
}

// ---------------- launch --------------------------------------------------------
extern "C" void kernel_launch(void* const* d_in, const int* in_sizes, int n_in,
                              void* d_out, int out_size)
{
    const float* x      = (const float*)d_in[0];
    const float* Wscore = (const float*)d_in[1];
    const float* Bscore = (const float*)d_in[2];
    const float* Wcap   = (const float*)d_in[3];
    const float* Bcap   = (const float*)d_in[4];
    const float* Wvote  = (const float*)d_in[5];
    const float* Bvote  = (const float*)d_in[6];
    const float* bu     = (const float*)d_in[7];
    const float* bi     = (const float*)d_in[8];
    float* out = (float*)d_out;

    const int dyn_smem = VSM_TOT * (int)sizeof(float);   // 180736 B
    cudaFuncSetAttribute(votetr_kernel, cudaFuncAttributeMaxDynamicSharedMemorySize, dyn_smem);

    front_kernel<<<L * 2, 256>>>(x, Wscore, Bscore, Wcap, Bcap);
    votetr_kernel<<<L, 512, dyn_smem>>>(Wvote, Bvote);

    // iters = 3: E0(uniform streaming), route+E ×2
    em0_kernel<<<NB * NCH, 256>>>(bu);
    fin_kernel<<<NB * 4, 512>>>(bi, 0, out);
    re_kernel<<<NB * NCH, 256>>>(bu);
    fin_kernel<<<NB * 4, 512>>>(bi, 0, out);
    re_kernel<<<NB * NCH, 256>>>(bu);
    fin_kernel<<<NB * 4, 512>>>(bi, 1, out);
}